// round 1
// baseline (speedup 1.0000x reference)
#include <cuda_runtime.h>
#include <math.h>

// Problem constants
#define BZ 64       // batch
#define SQ 1024     // seq len
#define HD 512      // hidden
#define GT 2048     // 4*H gate width
#define KD 512      // input size (== hidden here)
#define NCTA 128    // persistent CTAs in recurrence

// Scratch (static device allocations -- cudaMalloc is banned)
__device__ float g_xW[(size_t)SQ * GT * BZ];   // [s][n][b]  input projections
__device__ float g_hT[2][KD * BZ];             // double-buffered h, [k][b]
__device__ unsigned g_ready[SQ + 2];           // per-step arrival counters

// ---------------------------------------------------------------------------
// Init: zero h buffers and barrier counters (runs every graph replay)
// ---------------------------------------------------------------------------
__global__ void init_kernel() {
    int i = blockIdx.x * blockDim.x + threadIdx.x;
    if (i < KD * BZ) { g_hT[0][i] = 0.f; g_hT[1][i] = 0.f; }
    if (i < SQ + 2) g_ready[i] = 0u;
}

// ---------------------------------------------------------------------------
// Phase 1: xW[s][n][b] = sum_k x[b][s][k] * W[k][n] + bias[n]
// Tile: 64(b) x 128(n) per CTA, K-chunks of 32, 256 threads, 4x8 register tile
// ---------------------------------------------------------------------------
__global__ __launch_bounds__(256) void xw_gemm(const float* __restrict__ x,
                                               const float* __restrict__ W,
                                               const float* __restrict__ bias) {
    __shared__ float sAT[32][65];    // [kk][b], padded -> conflict-free transpose stores
    __shared__ float sB[32][128];    // [kk][n]

    const int s  = blockIdx.y;
    const int n0 = blockIdx.x * 128;
    const int tid = threadIdx.x;
    const int tx = tid & 15;    // column group: 8 cols each
    const int ty = tid >> 4;    // row group: 4 rows each

    float acc[4][8] = {};

    for (int k0 = 0; k0 < KD; k0 += 32) {
        // load x chunk (transposed into smem): 64 b x 32 k
        #pragma unroll
        for (int h = 0; h < 2; h++) {
            int b  = h * 32 + (tid >> 3);
            int cc = tid & 7;
            float4 v = *(const float4*)(x + ((size_t)b * SQ + s) * KD + k0 + cc * 4);
            sAT[cc * 4 + 0][b] = v.x;
            sAT[cc * 4 + 1][b] = v.y;
            sAT[cc * 4 + 2][b] = v.z;
            sAT[cc * 4 + 3][b] = v.w;
        }
        // load W chunk: 32 k x 128 n (direct, coalesced)
        #pragma unroll
        for (int h = 0; h < 4; h++) {
            int kk = h * 8 + (tid >> 5);
            int nn = (tid & 31) * 4;
            *(float4*)&sB[kk][nn] = *(const float4*)(W + (size_t)(k0 + kk) * GT + n0 + nn);
        }
        __syncthreads();

        #pragma unroll 8
        for (int kk = 0; kk < 32; kk++) {
            float aa[4];
            #pragma unroll
            for (int i = 0; i < 4; i++) aa[i] = sAT[kk][ty * 4 + i];
            float4 b1 = *(float4*)&sB[kk][tx * 8];
            float4 b2 = *(float4*)&sB[kk][tx * 8 + 4];
            float bb[8] = {b1.x, b1.y, b1.z, b1.w, b2.x, b2.y, b2.z, b2.w};
            #pragma unroll
            for (int i = 0; i < 4; i++)
                #pragma unroll
                for (int j = 0; j < 8; j++)
                    acc[i][j] += aa[i] * bb[j];
        }
        __syncthreads();
    }

    // epilogue: add bias, store as [s][n][b] (float4 along b)
    #pragma unroll
    for (int j = 0; j < 8; j++) {
        int n = n0 + tx * 8 + j;
        float bs = __ldg(bias + n);
        float4 o = make_float4(acc[0][j] + bs, acc[1][j] + bs,
                               acc[2][j] + bs, acc[3][j] + bs);
        *(float4*)(g_xW + ((size_t)s * GT + n) * BZ + ty * 4) = o;
    }
}

// ---------------------------------------------------------------------------
// Phase 2: persistent LSTM recurrence.
// 128 CTAs; CTA owns h-cols [4*blk, 4*blk+4) -> 16 gate columns.
// Per step: gates = xW[t] + h @ U_slice, then elementwise LSTM update.
// Device-wide sync via g_ready counters; h double-buffered in g_hT.
// ---------------------------------------------------------------------------
__device__ __forceinline__ float sigmoidf_(float v) {
    return 1.f / (1.f + __expf(-v));
}

__global__ __launch_bounds__(256, 1) void lstm_rec(const float* __restrict__ U,
                                                   float* __restrict__ out,
                                                   int has_hc) {
    extern __shared__ float sm[];
    float* Us  = sm;                  // [512][16] U slice (resident whole kernel)
    float* hs  = Us + KD * 16;        // [512][64] h staging for this step
    float* red = hs + KD * BZ;        // [4][16][64] k-group partials

    const int tid = threadIdx.x;
    const int hc0 = blockIdx.x * 4;   // first h-column owned by this CTA

    // Load U slice once: Us[k][col], col = g*4 + t  ->  gate col g*512 + hc0 + t
    for (int idx = tid; idx < KD * 16; idx += 256) {
        int k = idx >> 4, col = idx & 15;
        int gc = (col >> 2) * HD + hc0 + (col & 3);
        Us[idx] = __ldg(U + (size_t)k * GT + gc);
    }

    // GEMM ownership: 4 k-groups of 64 threads; 4b x 4col register tile each
    const int kg = tid >> 6;
    const int u  = tid & 63;
    const int b0 = (u & 15) * 4;
    const int c0 = (u >> 4) * 4;

    // Elementwise ownership: thread <-> (b, local h-col), fixed for all steps
    const int eb = tid & 63;
    const int jl = tid >> 2 >> 4;     // tid >> 6
    const int j  = hc0 + jl;

    float c_reg = 0.f;                // cell state lives in a register

    float* out_hs = out;                              // [B][S][H]
    float* out_ht = out + (size_t)BZ * SQ * HD;
    float* out_ct = out_ht + (size_t)BZ * HD;

    __syncthreads();

    for (int t = 0; t < SQ; t++) {
        // wait for all CTAs to have published h_t (t=0: zeros from init)
        if (t > 0) {
            if (tid == 0) {
                volatile unsigned* r = &g_ready[t];
                while (*r < (unsigned)NCTA) __nanosleep(128);
            }
            __syncthreads();
            __threadfence();
        }

        // stage full h_t (128 KB) into smem; .cg bypasses stale L1
        const float* hsrc = g_hT[t & 1];
        #pragma unroll
        for (int r = 0; r < 32; r++) {
            int off = (r * 256 + tid) * 4;
            float4 v = __ldcg((const float4*)(hsrc + off));
            *(float4*)(hs + off) = v;
        }
        __syncthreads();

        // partial GEMM over this group's k range
        float acc[4][4] = {};
        const float* hp = hs + (kg * 128) * BZ + b0;
        const float* up = Us + (kg * 128) * 16 + c0;
        #pragma unroll 8
        for (int kk = 0; kk < 128; kk++) {
            float4 h4 = *(const float4*)(hp + kk * BZ);
            float4 u4 = *(const float4*)(up + kk * 16);
            float hh[4] = {h4.x, h4.y, h4.z, h4.w};
            float uu[4] = {u4.x, u4.y, u4.z, u4.w};
            #pragma unroll
            for (int i = 0; i < 4; i++)
                #pragma unroll
                for (int jj = 0; jj < 4; jj++)
                    acc[i][jj] += hh[i] * uu[jj];
        }

        // publish partials
        #pragma unroll
        for (int jj = 0; jj < 4; jj++) {
            float4 v = make_float4(acc[0][jj], acc[1][jj], acc[2][jj], acc[3][jj]);
            *(float4*)&red[(kg * 16 + c0 + jj) * BZ + b0] = v;
        }
        __syncthreads();

        // elementwise LSTM update for (eb, j)
        float gate[4];
        #pragma unroll
        for (int g = 0; g < 4; g++) {
            int col = g * 4 + jl;
            float sg = red[(0 * 16 + col) * BZ + eb]
                     + red[(1 * 16 + col) * BZ + eb]
                     + red[(2 * 16 + col) * BZ + eb]
                     + red[(3 * 16 + col) * BZ + eb];
            int gc = g * HD + j;
            sg += __ldcs(g_xW + ((size_t)t * GT + gc) * BZ + eb);
            gate[g] = sg;
        }
        float ig = sigmoidf_(gate[0]);
        float fg = sigmoidf_(gate[1]);
        float gg = tanhf(gate[2]);
        float og = sigmoidf_(gate[3]);
        c_reg = fg * c_reg + ig * gg;
        float hv = og * tanhf(c_reg);

        // write h_{t+1}: state buffer (other parity) + hidden_seq output
        g_hT[(t + 1) & 1][j * BZ + eb] = hv;
        out_hs[((size_t)eb * SQ + t) * HD + j] = hv;
        if (has_hc && t == SQ - 1) {
            out_ht[(size_t)eb * HD + j] = hv;
            out_ct[(size_t)eb * HD + j] = c_reg;
        }

        // ensure red reads done + h stores visible, then arrive
        __threadfence();
        __syncthreads();
        if (tid == 0) atomicAdd(&g_ready[t + 1], 1u);
    }
}

// ---------------------------------------------------------------------------
// Launch
// ---------------------------------------------------------------------------
extern "C" void kernel_launch(void* const* d_in, const int* in_sizes, int n_in,
                              void* d_out, int out_size) {
    const float* x    = (const float*)d_in[0];
    const float* W    = (const float*)d_in[1];
    const float* U    = (const float*)d_in[2];
    const float* bias = (const float*)d_in[3];
    float* out = (float*)d_out;

    const int smem_rec = (KD * 16 + KD * BZ + 4 * 16 * BZ) * (int)sizeof(float); // 180224 B
    cudaFuncSetAttribute(lstm_rec, cudaFuncAttributeMaxDynamicSharedMemorySize, smem_rec);

    int has_hc = (out_size >= (int)((size_t)BZ * SQ * HD + 2 * BZ * HD)) ? 1 : 0;

    init_kernel<<<(KD * BZ + 255) / 256, 256>>>();
    xw_gemm<<<dim3(GT / 128, SQ), 256>>>(x, W, bias);
    lstm_rec<<<NCTA, 256, smem_rec>>>(U, out, has_hc);
}

// round 2
// speedup vs baseline: 1.1028x; 1.1028x over previous
#include <cuda_runtime.h>
#include <math.h>

// Problem constants
#define BZ 64       // batch
#define SQ 1024     // seq len
#define HD 512      // hidden
#define GT 2048     // 4*H gate width
#define KD 512      // input size (== hidden here)
#define NCTA 128    // persistent CTAs in recurrence

// Scratch (static device allocations -- cudaMalloc is banned)
__device__ float g_xW[(size_t)SQ * GT * BZ];   // [s][n][b]  input projections
__device__ float g_hT[2][KD * BZ];             // double-buffered h, [k][b]
__device__ unsigned g_ready[SQ + 2];           // per-step arrival counters

// ---------------------------------------------------------------------------
// Packed fp32x2 helpers (Blackwell f32x2 pipe -- 2 lane-FMAs per instruction)
// ---------------------------------------------------------------------------
typedef unsigned long long ull;

__device__ __forceinline__ ull pack2(float lo, float hi) {
    ull r;
    asm("mov.b64 %0, {%1, %2};" : "=l"(r) : "f"(lo), "f"(hi));
    return r;
}
__device__ __forceinline__ void fma2(ull& d, ull a, ull b) {
    asm("fma.rn.f32x2 %0, %1, %2, %0;" : "+l"(d) : "l"(a), "l"(b));
}
__device__ __forceinline__ float2 unpack2(ull v) {
    float2 f;
    asm("mov.b64 {%0, %1}, %2;" : "=f"(f.x), "=f"(f.y) : "l"(v));
    return f;
}
__device__ __forceinline__ float sigmoidf_(float v) {
    return 1.f / (1.f + __expf(-v));
}
__device__ __forceinline__ float tanh_fast(float v) {
    float r;
    asm("tanh.approx.f32 %0, %1;" : "=f"(r) : "f"(v));
    return r;
}

// ---------------------------------------------------------------------------
// Init: zero h buffers and barrier counters (runs every graph replay)
// ---------------------------------------------------------------------------
__global__ void init_kernel() {
    int i = blockIdx.x * blockDim.x + threadIdx.x;
    if (i < KD * BZ) { g_hT[0][i] = 0.f; g_hT[1][i] = 0.f; }
    if (i < SQ + 2) g_ready[i] = 0u;
}

// ---------------------------------------------------------------------------
// Phase 1: xW[s][n][b] = sum_k x[b][s][k] * W[k][n] + bias[n]
// Tile: 64(b) x 128(n) per CTA, K-chunks of 32, 256 threads, 4x8 reg tile.
// Inner product uses fma.rn.f32x2: a broadcast-packed, b as double2 from smem.
// ---------------------------------------------------------------------------
__global__ __launch_bounds__(256) void xw_gemm(const float* __restrict__ x,
                                               const float* __restrict__ W,
                                               const float* __restrict__ bias) {
    __shared__ __align__(16) float sAT[32][68];   // [kk][b], 272B rows keep float4 aligned
    __shared__ __align__(16) float sB[32][128];   // [kk][n]

    const int s  = blockIdx.y;
    const int n0 = blockIdx.x * 128;
    const int tid = threadIdx.x;
    const int tx = tid & 15;    // column group: 8 cols each
    const int ty = tid >> 4;    // row group: 4 rows each

    ull acc2[4][4] = {};        // [b-row][col-pair]  (8 cols as 4 packed pairs)

    for (int k0 = 0; k0 < KD; k0 += 32) {
        // load x chunk (transposed into smem): 64 b x 32 k
        #pragma unroll
        for (int h = 0; h < 2; h++) {
            int b  = h * 32 + (tid >> 3);
            int cc = tid & 7;
            float4 v = *(const float4*)(x + ((size_t)b * SQ + s) * KD + k0 + cc * 4);
            sAT[cc * 4 + 0][b] = v.x;
            sAT[cc * 4 + 1][b] = v.y;
            sAT[cc * 4 + 2][b] = v.z;
            sAT[cc * 4 + 3][b] = v.w;
        }
        // load W chunk: 32 k x 128 n (direct, coalesced)
        #pragma unroll
        for (int h = 0; h < 4; h++) {
            int kk = h * 8 + (tid >> 5);
            int nn = (tid & 31) * 4;
            *(float4*)&sB[kk][nn] = *(const float4*)(W + (size_t)(k0 + kk) * GT + n0 + nn);
        }
        __syncthreads();

        #pragma unroll 8
        for (int kk = 0; kk < 32; kk++) {
            float4 a4 = *(const float4*)&sAT[kk][ty * 4];     // broadcast within half-warp
            ull a2[4];
            a2[0] = pack2(a4.x, a4.x);
            a2[1] = pack2(a4.y, a4.y);
            a2[2] = pack2(a4.z, a4.z);
            a2[3] = pack2(a4.w, a4.w);
            // b pairs come pre-packed straight out of LDS.128
            double2 bl = *(const double2*)&sB[kk][tx * 8];
            double2 bh = *(const double2*)&sB[kk][tx * 8 + 4];
            ull bp[4];
            bp[0] = __double_as_longlong(bl.x);
            bp[1] = __double_as_longlong(bl.y);
            bp[2] = __double_as_longlong(bh.x);
            bp[3] = __double_as_longlong(bh.y);
            #pragma unroll
            for (int i = 0; i < 4; i++)
                #pragma unroll
                for (int p = 0; p < 4; p++)
                    fma2(acc2[i][p], a2[i], bp[p]);
        }
        __syncthreads();
    }

    // epilogue: unpack, add bias, store as [s][n][b] (float4 along b)
    float acc[4][8];
    #pragma unroll
    for (int i = 0; i < 4; i++)
        #pragma unroll
        for (int p = 0; p < 4; p++) {
            float2 f = unpack2(acc2[i][p]);
            acc[i][2 * p]     = f.x;
            acc[i][2 * p + 1] = f.y;
        }
    #pragma unroll
    for (int j = 0; j < 8; j++) {
        int n = n0 + tx * 8 + j;
        float bs = __ldg(bias + n);
        float4 o = make_float4(acc[0][j] + bs, acc[1][j] + bs,
                               acc[2][j] + bs, acc[3][j] + bs);
        *(float4*)(g_xW + ((size_t)s * GT + n) * BZ + ty * 4) = o;
    }
}

// ---------------------------------------------------------------------------
// Phase 2: persistent LSTM recurrence.
// 128 CTAs; CTA owns h-cols [4*blk, 4*blk+4) -> 16 gate columns.
// Per step: gates = xW[t] + h @ U_slice, then elementwise LSTM update.
// Device-wide sync via g_ready counters; h double-buffered in g_hT.
// ---------------------------------------------------------------------------
__global__ __launch_bounds__(256, 1) void lstm_rec(const float* __restrict__ U,
                                                   float* __restrict__ out,
                                                   int has_hc) {
    extern __shared__ __align__(16) float sm[];
    float* Us  = sm;                  // [512][16] U slice (resident whole kernel)
    float* hs  = Us + KD * 16;        // [512][64] h staging for this step
    float* red = hs + KD * BZ;        // [4][16][64] k-group partials

    const int tid = threadIdx.x;
    const int hc0 = blockIdx.x * 4;   // first h-column owned by this CTA

    // Load U slice once: Us[k][col], col = g*4 + t  ->  gate col g*512 + hc0 + t
    for (int idx = tid; idx < KD * 16; idx += 256) {
        int k = idx >> 4, col = idx & 15;
        int gc = (col >> 2) * HD + hc0 + (col & 3);
        Us[idx] = __ldg(U + (size_t)k * GT + gc);
    }

    // GEMM ownership: 4 k-groups of 64 threads; 4b x 4col register tile each
    const int kg = tid >> 6;
    const int u  = tid & 63;
    const int b0 = (u & 15) * 4;
    const int c0 = (u >> 4) * 4;

    // Elementwise ownership: thread <-> (b, local h-col), fixed for all steps
    const int eb = tid & 63;
    const int jl = tid >> 6;
    const int j  = hc0 + jl;

    float c_reg = 0.f;                // cell state lives in a register

    float* out_hs = out;                              // [B][S][H]
    float* out_ht = out + (size_t)BZ * SQ * HD;
    float* out_ct = out_ht + (size_t)BZ * HD;

    __syncthreads();

    for (int t = 0; t < SQ; t++) {
        // wait for all CTAs to have published h_t (t=0: zeros from init)
        if (t > 0) {
            if (tid == 0) {
                volatile unsigned* r = &g_ready[t];
                while (*r < (unsigned)NCTA) { }
            }
            __syncthreads();
            __threadfence();
        }

        // stage full h_t (128 KB) into smem; .cg bypasses stale L1
        const float* hsrc = g_hT[t & 1];
        #pragma unroll
        for (int r = 0; r < 32; r++) {
            int off = (r * 256 + tid) * 4;
            float4 v = __ldcg((const float4*)(hsrc + off));
            *(float4*)(hs + off) = v;
        }
        __syncthreads();

        // prefetch this thread's xW gate terms (independent of h) to hide L2
        float xwv[4];
        #pragma unroll
        for (int g = 0; g < 4; g++) {
            int gc = g * HD + j;
            xwv[g] = __ldcs(g_xW + ((size_t)t * GT + gc) * BZ + eb);
        }

        // partial GEMM over this group's k range (packed f32x2 FMA)
        ull acc2[4][2] = {};          // [b-row][col-pair]
        const float* hp = hs + (kg * 128) * BZ + b0;
        const float* up = Us + (kg * 128) * 16 + c0;
        #pragma unroll 8
        for (int kk = 0; kk < 128; kk++) {
            float4 h4 = *(const float4*)(hp + kk * BZ);
            double2 u2 = *(const double2*)(up + kk * 16);   // col pairs, pre-packed
            ull ub[2] = { __double_as_longlong(u2.x), __double_as_longlong(u2.y) };
            ull hb[4];
            hb[0] = pack2(h4.x, h4.x);
            hb[1] = pack2(h4.y, h4.y);
            hb[2] = pack2(h4.z, h4.z);
            hb[3] = pack2(h4.w, h4.w);
            #pragma unroll
            for (int i = 0; i < 4; i++) {
                fma2(acc2[i][0], hb[i], ub[0]);
                fma2(acc2[i][1], hb[i], ub[1]);
            }
        }

        // publish partials
        float2 fa[4][2];
        #pragma unroll
        for (int i = 0; i < 4; i++) {
            fa[i][0] = unpack2(acc2[i][0]);
            fa[i][1] = unpack2(acc2[i][1]);
        }
        #pragma unroll
        for (int jj = 0; jj < 4; jj++) {
            float4 v;
            v.x = (jj & 1) ? fa[0][jj >> 1].y : fa[0][jj >> 1].x;
            v.y = (jj & 1) ? fa[1][jj >> 1].y : fa[1][jj >> 1].x;
            v.z = (jj & 1) ? fa[2][jj >> 1].y : fa[2][jj >> 1].x;
            v.w = (jj & 1) ? fa[3][jj >> 1].y : fa[3][jj >> 1].x;
            *(float4*)&red[(kg * 16 + c0 + jj) * BZ + b0] = v;
        }
        __syncthreads();

        // elementwise LSTM update for (eb, j)
        float gate[4];
        #pragma unroll
        for (int g = 0; g < 4; g++) {
            int col = g * 4 + jl;
            gate[g] = xwv[g]
                    + red[(0 * 16 + col) * BZ + eb]
                    + red[(1 * 16 + col) * BZ + eb]
                    + red[(2 * 16 + col) * BZ + eb]
                    + red[(3 * 16 + col) * BZ + eb];
        }
        float ig = sigmoidf_(gate[0]);
        float fg = sigmoidf_(gate[1]);
        float gg = tanh_fast(gate[2]);
        float og = sigmoidf_(gate[3]);
        c_reg = fg * c_reg + ig * gg;
        float hv = og * tanh_fast(c_reg);

        // publish h_{t+1} (critical path), then arrive
        g_hT[(t + 1) & 1][j * BZ + eb] = hv;
        __threadfence();
        __syncthreads();
        if (tid == 0) atomicAdd(&g_ready[t + 1], 1u);

        // off-critical-path output stores
        out_hs[((size_t)eb * SQ + t) * HD + j] = hv;
        if (has_hc && t == SQ - 1) {
            out_ht[(size_t)eb * HD + j] = hv;
            out_ct[(size_t)eb * HD + j] = c_reg;
        }
    }
}

// ---------------------------------------------------------------------------
// Launch
// ---------------------------------------------------------------------------
extern "C" void kernel_launch(void* const* d_in, const int* in_sizes, int n_in,
                              void* d_out, int out_size) {
    const float* x    = (const float*)d_in[0];
    const float* W    = (const float*)d_in[1];
    const float* U    = (const float*)d_in[2];
    const float* bias = (const float*)d_in[3];
    float* out = (float*)d_out;

    const int smem_rec = (KD * 16 + KD * BZ + 4 * 16 * BZ) * (int)sizeof(float); // 180224 B
    cudaFuncSetAttribute(lstm_rec, cudaFuncAttributeMaxDynamicSharedMemorySize, smem_rec);

    int has_hc = (out_size >= (int)((size_t)BZ * SQ * HD + 2 * BZ * HD)) ? 1 : 0;

    init_kernel<<<(KD * BZ + 255) / 256, 256>>>();
    xw_gemm<<<dim3(GT / 128, SQ), 256>>>(x, W, bias);
    lstm_rec<<<NCTA, 256, smem_rec>>>(U, out, has_hc);
}